// round 16
// baseline (speedup 1.0000x reference)
#include <cuda_runtime.h>
#include <cuda_bf16.h>
#include <math.h>
#include <stdint.h>

// ---------------- problem constants ----------------
#define BB   4
#define TT   512
#define DM   1024
#define HH   16
#define DH   64
#define FF   2048
#define EE   8
#define NTOK 2048
#define EPSL 1e-5f

// GEMM tiling (round-8 proven config)
#define BM 128
#define BN 128
#define BKT 16
#define AS_STRIDE 20
#define BS_STRIDE 136
#define NSTAGE 3
#define A_ELEMS (BM * AS_STRIDE)
#define B_ELEMS (BKT * BS_STRIDE)
#define GEMM_SMEM (NSTAGE * (A_ELEMS + B_ELEMS) * 4)   // 56832

// ---------------- static scratch ----------------
__device__ float g_q   [NTOK * DM];
__device__ float g_k   [NTOK * DM];
__device__ float g_v   [NTOK * DM];
__device__ float g_k2  [NTOK * DM];
__device__ float g_v2  [NTOK * DM];
__device__ float g_ctx [NTOK * DM];
__device__ float g_attn[NTOK * DM];
__device__ float g_ps  [NTOK * DM];     // split-K partial buffer
__device__ float g_t1  [NTOK * DM];
__device__ float g_t1t [NTOK * DM];
__device__ float g_t2  [NTOK * DM];
__device__ float g_t2t [NTOK * DM];
__device__ float g_ys  [NTOK * 2 * DM];
__device__ float g_h   [(size_t)EE * NTOK * FF];
__device__ int   g_elist[EE * NTOK];
__device__ int   g_slot [EE * NTOK];
__device__ float g_egate[EE * NTOK];
__device__ int   g_ecnt [EE];
__device__ float g_imp  [EE];

// ---------------- helpers ----------------
__device__ __forceinline__ uint32_t f2tf(float f) {
    uint32_t u;
    asm("cvt.rna.tf32.f32 %0, %1;" : "=r"(u) : "f"(f));
    return u;
}
__device__ __forceinline__ float tfr(float f) { return __uint_as_float(f2tf(f)); }

__device__ __forceinline__ void mma8(float* c, const uint32_t* a, const uint32_t* b) {
    asm volatile(
        "mma.sync.aligned.m16n8k8.row.col.f32.tf32.tf32.f32 "
        "{%0,%1,%2,%3}, {%4,%5,%6,%7}, {%8,%9}, {%0,%1,%2,%3};\n"
        : "+f"(c[0]), "+f"(c[1]), "+f"(c[2]), "+f"(c[3])
        : "r"(a[0]), "r"(a[1]), "r"(a[2]), "r"(a[3]), "r"(b[0]), "r"(b[1]));
}

__device__ __forceinline__ uint32_t smem_u32(const void* p) {
    return (uint32_t)__cvta_generic_to_shared(p);
}
__device__ __forceinline__ void cp16(uint32_t dst, const void* src, bool pred) {
    int sz = pred ? 16 : 0;
    asm volatile("cp.async.cg.shared.global [%0], [%1], 16, %2;\n"
                 :: "r"(dst), "l"(src), "r"(sz) : "memory");
}
#define CP_COMMIT  asm volatile("cp.async.commit_group;\n" ::: "memory")
#define CP_WAIT1   asm volatile("cp.async.wait_group 1;\n" ::: "memory")
#define CP_WAIT0   asm volatile("cp.async.wait_group 0;\n" ::: "memory")

__device__ __forceinline__ float block_reduce_sum(float v, float* red) {
    int lane = threadIdx.x & 31, w = threadIdx.x >> 5;
    #pragma unroll
    for (int o = 16; o; o >>= 1) v += __shfl_xor_sync(0xFFFFFFFFu, v, o);
    __syncthreads();
    if (lane == 0) red[w] = v;
    __syncthreads();
    if (w == 0) {
        v = (lane < ((int)blockDim.x >> 5)) ? red[lane] : 0.0f;
        #pragma unroll
        for (int o = 16; o; o >>= 1) v += __shfl_xor_sync(0xFFFFFFFFu, v, o);
        if (lane == 0) red[0] = v;
    }
    __syncthreads();
    return red[0];
}

// ---------------- tiny zero ----------------
__global__ void zero_small_kernel() {
    int i = threadIdx.x;
    if (i < EE) { g_ecnt[i] = 0; g_imp[i] = 0.0f; }
}

// ================= tf32 MMA GEMM core =================
// MODE 0: +bias, rna-rounded out; MODE 1: moe gather+relu, rounded out;
// MODE 2: moe slot-scatter (fp32 out); MODE 4: raw partial (fp32, no bias)
template<int MODE>
__device__ __forceinline__ void gemm_core(
    const float* __restrict__ A, const float* __restrict__ W,
    const float* __restrict__ bias, float* __restrict__ C,
    int K, int N, int row0, int col0, int koff, int Kloop,
    const int* atoks, const int* slots, const float* gates)
{
    extern __shared__ uint32_t smp[];
    uint32_t* As = smp;
    uint32_t* Bs = smp + NSTAGE * A_ELEMS;

    const int tid  = threadIdx.x;
    const int lane = tid & 31;
    const int wid  = tid >> 5;
    const int wm   = wid >> 2;
    const int wn   = wid & 3;
    const int g    = lane >> 2;
    const int tig  = lane & 3;

    const int lr0 = tid >> 2;
    const int akq = (tid & 3) * 4;
    bool p0 = true, p1 = true;
    const float *a0p, *a1p;
    if (MODE == 1) {
        int t0 = atoks[lr0], t1 = atoks[lr0 + 64];
        p0 = (t0 >= 0); p1 = (t1 >= 0);
        a0p = A + (size_t)(p0 ? t0 : 0) * K + koff + akq;
        a1p = A + (size_t)(p1 ? t1 : 0) * K + koff + akq;
    } else {
        a0p = A + (size_t)(row0 + lr0) * K + koff + akq;
        a1p = A + (size_t)(row0 + lr0 + 64) * K + koff + akq;
    }

    const int kr = tid >> 4;
    const int nq = (tid & 15) * 8;
    const float* bp = W + (size_t)(koff + kr) * N + col0 + nq;

    uint32_t sA0 = smem_u32(As) + (lr0 * AS_STRIDE + akq) * 4;
    uint32_t sA1 = sA0 + 64 * AS_STRIDE * 4;
    uint32_t sB0 = smem_u32(Bs) + (kr * BS_STRIDE + nq) * 4;

    const int nk = Kloop / BKT;

#define ISSUE(b, kti) do {                                     \
        uint32_t ao = (uint32_t)(b) * (A_ELEMS * 4);           \
        cp16(sA0 + ao, a0p + (kti) * BKT, p0);                 \
        cp16(sA1 + ao, a1p + (kti) * BKT, p1);                 \
        const float* bs_ = bp + (size_t)(kti) * BKT * N;       \
        uint32_t bo = (uint32_t)(b) * (B_ELEMS * 4);           \
        cp16(sB0 + bo, bs_, true);                             \
        cp16(sB0 + bo + 16, bs_ + 4, true);                    \
    } while (0)

    ISSUE(0, 0); CP_COMMIT;
    ISSUE(1, 1); CP_COMMIT;

    float acc[4][4][4];
    #pragma unroll
    for (int i = 0; i < 4; i++)
        #pragma unroll
        for (int j = 0; j < 4; j++)
            #pragma unroll
            for (int r = 0; r < 4; r++) acc[i][j][r] = 0.0f;

    int buf = 0;
    for (int kt = 0; kt < nk; kt++) {
        CP_WAIT1;
        __syncthreads();
        if (kt + 2 < nk) {
            int nb = buf + 2; if (nb >= NSTAGE) nb -= NSTAGE;
            ISSUE(nb, kt + 2);
        }
        CP_COMMIT;

        const uint32_t* Ab = As + buf * A_ELEMS;
        const uint32_t* Bb = Bs + buf * B_ELEMS;
        #pragma unroll
        for (int k8 = 0; k8 < 2; k8++) {
            uint32_t af[4][4], bf[4][2];
            const uint32_t* abase = Ab + (wm * 64 + g) * AS_STRIDE + k8 * 8 + tig;
            #pragma unroll
            for (int mt = 0; mt < 4; mt++) {
                const uint32_t* p = abase + mt * 16 * AS_STRIDE;
                af[mt][0] = p[0];
                af[mt][1] = p[8 * AS_STRIDE];
                af[mt][2] = p[4];
                af[mt][3] = p[8 * AS_STRIDE + 4];
            }
            const uint32_t* bbase = Bb + (k8 * 8 + tig) * BS_STRIDE + wn * 32 + g;
            #pragma unroll
            for (int nt = 0; nt < 4; nt++) {
                bf[nt][0] = bbase[nt * 8];
                bf[nt][1] = bbase[4 * BS_STRIDE + nt * 8];
            }
            #pragma unroll
            for (int mt = 0; mt < 4; mt++)
                #pragma unroll
                for (int nt = 0; nt < 4; nt++)
                    mma8(acc[mt][nt], af[mt], bf[nt]);
        }
        buf = (buf == NSTAGE - 1) ? 0 : buf + 1;
    }
#undef ISSUE

    #pragma unroll
    for (int mt = 0; mt < 4; mt++) {
        const int lr = wm * 64 + mt * 16 + g;
        #pragma unroll
        for (int nt = 0; nt < 4; nt++) {
            float* ac = acc[mt][nt];
            const int c = col0 + wn * 32 + nt * 8 + 2 * tig;
            float bc0 = 0.f, bc1 = 0.f;
            if (MODE != 4) { bc0 = bias[c]; bc1 = bias[c + 1]; }
            if (MODE == 0) {
                *(float2*)&C[(size_t)(row0 + lr) * N + c]     = make_float2(tfr(ac[0] + bc0), tfr(ac[1] + bc1));
                *(float2*)&C[(size_t)(row0 + lr + 8) * N + c] = make_float2(tfr(ac[2] + bc0), tfr(ac[3] + bc1));
            } else if (MODE == 4) {
                *(float2*)&C[(size_t)(row0 + lr) * N + c]     = make_float2(ac[0], ac[1]);
                *(float2*)&C[(size_t)(row0 + lr + 8) * N + c] = make_float2(ac[2], ac[3]);
            } else if (MODE == 1) {
                if (atoks[lr] >= 0)
                    *(float2*)&C[(size_t)(row0 + lr) * N + c] = make_float2(
                        tfr(fmaxf(ac[0] + bc0, 0.f)), tfr(fmaxf(ac[1] + bc1, 0.f)));
                if (atoks[lr + 8] >= 0)
                    *(float2*)&C[(size_t)(row0 + lr + 8) * N + c] = make_float2(
                        tfr(fmaxf(ac[2] + bc0, 0.f)), tfr(fmaxf(ac[3] + bc1, 0.f)));
            } else {
                int sid = slots[lr]; float gt = gates[lr];
                if (sid >= 0)
                    *(float2*)&C[(size_t)sid * DM + c] =
                        make_float2(gt * (ac[0] + bc0), gt * (ac[1] + bc1));
                sid = slots[lr + 8]; gt = gates[lr + 8];
                if (sid >= 0)
                    *(float2*)&C[(size_t)sid * DM + c] =
                        make_float2(gt * (ac[2] + bc0), gt * (ac[3] + bc1));
            }
        }
    }
}

// ---------------- GEMM wrappers ----------------
// split-K(2) projection: z = K-half; raw fp32 partials to C0/C1
__global__ __launch_bounds__(256, 2) void proj_splitk_kernel(
    const float* A, const float* W, float* C0, float* C1)
{
    const int z = blockIdx.z;
    float* C = (z == 0) ? C0 : C1;
    gemm_core<4>(A, W, nullptr, C, DM, DM, blockIdx.y * BM, blockIdx.x * BN,
                 z * (DM / 2), DM / 2, nullptr, nullptr, nullptr);
}

// 5-way packed projections (sa_q, sa_k, sa_v, ca_k, ca_v), rna-rounded outputs
__global__ __launch_bounds__(256, 2) void proj_qkv5_kernel(
    const float* A0, const float* A1, const float* A2, const float* A3, const float* A4,
    const float* W0, const float* W1, const float* W2, const float* W3, const float* W4,
    const float* b0, const float* b1, const float* b2, const float* b3, const float* b4,
    float* C0, float* C1, float* C2, float* C3, float* C4, int K, int N)
{
    const int z = blockIdx.z;
    const float* A = (z == 0) ? A0 : (z == 1) ? A1 : (z == 2) ? A2 : (z == 3) ? A3 : A4;
    const float* W = (z == 0) ? W0 : (z == 1) ? W1 : (z == 2) ? W2 : (z == 3) ? W3 : W4;
    const float* b = (z == 0) ? b0 : (z == 1) ? b1 : (z == 2) ? b2 : (z == 3) ? b3 : b4;
    float*       C = (z == 0) ? C0 : (z == 1) ? C1 : (z == 2) ? C2 : (z == 3) ? C3 : C4;
    gemm_core<0>(A, W, b, C, K, N, blockIdx.y * BM, blockIdx.x * BN,
                 0, K, nullptr, nullptr, nullptr);
}

__global__ __launch_bounds__(256, 2) void moe1_kernel(
    const float* __restrict__ X, const float* __restrict__ w1,
    const float* __restrict__ b1)
{
    const int e = blockIdx.z;
    const int cnt = g_ecnt[e];
    const int row0 = blockIdx.y * BM;
    if (row0 >= cnt) return;
    __shared__ int toks[BM];
    if (threadIdx.x < BM) {
        int r = row0 + threadIdx.x;
        toks[threadIdx.x] = (r < cnt) ? g_elist[e * NTOK + r] : -1;
    }
    __syncthreads();
    gemm_core<1>(X, w1 + (size_t)e * DM * FF, b1 + e * FF,
                 g_h + (size_t)e * NTOK * FF,
                 DM, FF, row0, blockIdx.x * BN, 0, DM, toks, nullptr, nullptr);
}

__global__ __launch_bounds__(256, 2) void moe2_kernel(
    const float* __restrict__ w2, const float* __restrict__ b2)
{
    const int e = blockIdx.z;
    const int cnt = g_ecnt[e];
    const int row0 = blockIdx.y * BM;
    if (row0 >= cnt) return;
    __shared__ int slts[BM];
    __shared__ float gat[BM];
    if (threadIdx.x < BM) {
        int r = row0 + threadIdx.x;
        bool ok = (r < cnt);
        slts[threadIdx.x] = ok ? g_slot[e * NTOK + r] : -1;
        gat[threadIdx.x]  = ok ? g_egate[e * NTOK + r] : 0.0f;
    }
    __syncthreads();
    gemm_core<2>(g_h + (size_t)e * NTOK * FF, w2 + (size_t)e * FF * DM,
                 b2 + e * DM, g_ys,
                 FF, DM, row0, blockIdx.x * BN, 0, FF, nullptr, slts, gat);
}

// ---------------- tensor-core attention (512 threads, cp.async double-buffered) ----------------
// Q1 != nullptr: Q operand = tfr((Q+Q1+qb) * 0.125)
#define AQT   32
#define KT2   64
#define KSTR  68
#define VSTR  72
#define KVBUF (KT2 * VSTR)
#define SSTR  516
#define QF_ELEMS (2 * 8 * 32 * 4)
#define ATC_SMEM ((QF_ELEMS + 2 * KVBUF + AQT * SSTR) * 4)   // 111104 B

__global__ __launch_bounds__(512, 2) void attn_tc_kernel(
    const float* __restrict__ Q, const float* __restrict__ Q1,
    const float* __restrict__ qb,
    const float* __restrict__ Kk, const float* __restrict__ V,
    float* __restrict__ O)
{
    extern __shared__ float am[];
    uint32_t* Qf = (uint32_t*)am;
    float* KV = am + QF_ELEMS;
    float* S  = KV + 2 * KVBUF;

    const int q0  = blockIdx.x * AQT;
    const int h   = blockIdx.y;
    const int b   = blockIdx.z;
    const int tid = threadIdx.x;
    const int lane = tid & 31;
    const int wid  = tid >> 5;
    const int wm   = wid >> 3;
    const int wn   = wid & 7;
    const int g    = lane >> 2;
    const int tig  = lane & 3;

    const int lrow = tid >> 3;
    const int lc   = (tid & 7) * 8;
    const float* ksrc = Kk + ((size_t)(b * TT) + lrow) * DM + h * DH + lc;
    const float* vsrc = V  + ((size_t)(b * TT) + lrow) * DM + h * DH + lc;
    uint32_t kdst = smem_u32(KV) + (lrow * KSTR + lc) * 4;
    uint32_t vdst = smem_u32(KV) + (lrow * VSTR + lc) * 4;

#define ISSUE_K(bf_, kt_) do {                                         \
        const float* s_ = ksrc + (size_t)(kt_) * KT2 * DM;             \
        uint32_t d_ = kdst + (uint32_t)(bf_) * (KVBUF * 4);            \
        cp16(d_, s_, true); cp16(d_ + 16, s_ + 4, true);               \
    } while (0)
#define ISSUE_V(bf_, kt_) do {                                         \
        const float* s_ = vsrc + (size_t)(kt_) * KT2 * DM;             \
        uint32_t d_ = vdst + (uint32_t)(bf_) * (KVBUF * 4);            \
        cp16(d_, s_, true); cp16(d_ + 16, s_ + 4, true);               \
    } while (0)

    ISSUE_K(0, 0); CP_COMMIT;

    for (int i = tid; i < QF_ELEMS; i += 512) {
        int r     = i & 3;
        int lane_ = (i >> 2) & 31;
        int k8    = (i >> 7) & 7;
        int wmf   = i >> 10;
        int gg = lane_ >> 2, tt = lane_ & 3;
        int row = q0 + wmf * 16 + gg + (r & 1) * 8;
        int col = k8 * 8 + tt + (r >> 1) * 4;
        size_t idx = ((size_t)(b * TT + row)) * DM + h * DH + col;
        float v;
        if (Q1) v = tfr((Q[idx] + Q1[idx] + qb[h * DH + col]) * 0.125f);
        else    v = Q[idx] * 0.125f;   // Q already tf32 (rounded epilogue); x0.125 exact
        Qf[i] = __float_as_uint(v);
    }

    int buf = 0;
    for (int kt = 0; kt < TT / KT2; kt++) {
        const bool more = (kt + 1 < TT / KT2);
        if (more) { ISSUE_K(buf ^ 1, kt + 1); CP_COMMIT; }
        if (more) { CP_WAIT1; } else { CP_WAIT0; }
        __syncthreads();

        const float* Kb = KV + buf * KVBUF;
        float c[4] = {0.f, 0.f, 0.f, 0.f};
        #pragma unroll
        for (int k8 = 0; k8 < DH / 8; k8++) {
            uint32_t af[4];
            *(uint4*)af = *(const uint4*)(Qf + ((wm * 8 + k8) * 32 + lane) * 4);
            const uint32_t* bb = (const uint32_t*)(Kb + (wn * 8 + g) * KSTR + k8 * 8 + tig);
            uint32_t bf2[2] = { bb[0], bb[4] };
            mma8(c, af, bf2);
        }
        int col = kt * KT2 + wn * 8 + 2 * tig;
        float* s0 = S + (wm * 16 + g) * SSTR + col;
        float* s1 = S + (wm * 16 + g + 8) * SSTR + col;
        s0[0] = c[0]; s0[1] = c[1];
        s1[0] = c[2]; s1[1] = c[3];
        __syncthreads();
        buf ^= 1;
    }

    ISSUE_V(0, 0); CP_COMMIT;

    #pragma unroll
    for (int rr = 0; rr < 2; rr++) {
        int row = wid * 2 + rr;
        float* sr = S + row * SSTR;
        float m = -1e30f;
        for (int j = lane; j < TT; j += 32) m = fmaxf(m, sr[j]);
        #pragma unroll
        for (int o = 16; o; o >>= 1) m = fmaxf(m, __shfl_xor_sync(0xFFFFFFFFu, m, o));
        float sum = 0.0f;
        for (int j = lane; j < TT; j += 32) { float ev = __expf(sr[j] - m); sr[j] = ev; sum += ev; }
        #pragma unroll
        for (int o = 16; o; o >>= 1) sum += __shfl_xor_sync(0xFFFFFFFFu, sum, o);
        float inv = 1.0f / sum;
        for (int j = lane; j < TT; j += 32) sr[j] = tfr(sr[j] * inv);
    }

    float acc[4] = {0.f, 0.f, 0.f, 0.f};
    buf = 0;
    for (int vt = 0; vt < TT / KT2; vt++) {
        const bool more = (vt + 1 < TT / KT2);
        if (more) { ISSUE_V(buf ^ 1, vt + 1); CP_COMMIT; }
        if (more) { CP_WAIT1; } else { CP_WAIT0; }
        __syncthreads();

        const float* Vb = KV + buf * KVBUF;
        #pragma unroll
        for (int k8 = 0; k8 < KT2 / 8; k8++) {
            uint32_t af[4];
            const uint32_t* ab = (const uint32_t*)(S + (wm * 16 + g) * SSTR + vt * KT2 + k8 * 8 + tig);
            af[0] = ab[0]; af[1] = ab[8 * SSTR]; af[2] = ab[4]; af[3] = ab[8 * SSTR + 4];
            const uint32_t* bb = (const uint32_t*)(Vb + (k8 * 8 + tig) * VSTR + wn * 8 + g);
            uint32_t bf2[2] = { bb[0], bb[4 * VSTR] };
            mma8(acc, af, bf2);
        }
        __syncthreads();
        buf ^= 1;
    }
#undef ISSUE_K
#undef ISSUE_V

    {
        int col = h * DH + wn * 8 + 2 * tig;
        size_t r0 = (size_t)(b * TT + q0 + wm * 16 + g) * DM + col;
        size_t r1 = (size_t)(b * TT + q0 + wm * 16 + g + 8) * DM + col;
        O[r0]     = tfr(acc[0]); O[r0 + 1] = tfr(acc[1]);
        O[r1]     = tfr(acc[2]); O[r1 + 1] = tfr(acc[3]);
    }
}

// ---------------- add(2 partials + bias) + layernorm (dual output) ----------------
__global__ __launch_bounds__(256) void add_ln2_kernel(
    const float* __restrict__ x0, const float* __restrict__ x1,
    const float* __restrict__ xb, const float* __restrict__ r,
    const float* __restrict__ g, const float* __restrict__ be,
    float* __restrict__ out, float* __restrict__ out_t)
{
    __shared__ float red[32];
    __shared__ float s_mean, s_rstd;
    int row = blockIdx.x, tid = threadIdx.x;
    const float* p0 = x0 + (size_t)row * DM;
    const float* p1 = x1 + (size_t)row * DM;
    const float* rp = r + (size_t)row * DM;
    float v[4]; float sum = 0.0f;
    #pragma unroll
    for (int i = 0; i < 4; i++) {
        int idx = tid + i * 256;
        v[i] = (p0[idx] + p1[idx] + xb[idx]) + rp[idx];
        sum += v[i];
    }
    sum = block_reduce_sum(sum, red);
    if (tid == 0) s_mean = sum * (1.0f / DM);
    __syncthreads();
    float mean = s_mean, vs = 0.0f;
    #pragma unroll
    for (int i = 0; i < 4; i++) { float dv = v[i] - mean; vs += dv * dv; }
    vs = block_reduce_sum(vs, red);
    if (tid == 0) s_rstd = rsqrtf(vs * (1.0f / DM) + EPSL);
    __syncthreads();
    float rs = s_rstd;
    #pragma unroll
    for (int i = 0; i < 4; i++) {
        int idx = tid + i * 256;
        float o = (v[i] - mean) * rs * g[idx] + be[idx];
        out[(size_t)row * DM + idx] = o;
        if (out_t) out_t[(size_t)row * DM + idx] = tfr(o);
    }
}

// ---------------- add(2 partials + bias) + layernorm + fused router (LN2, dual out) ----------------
__global__ __launch_bounds__(256) void add_ln2_router_kernel(
    const float* __restrict__ x0, const float* __restrict__ x1,
    const float* __restrict__ xb, const float* __restrict__ r,
    const float* __restrict__ g, const float* __restrict__ be,
    float* __restrict__ out, float* __restrict__ out_t,
    const float* __restrict__ rw, const float* __restrict__ rb)
{
    __shared__ float red[32];
    __shared__ float s_mean, s_rstd;
    __shared__ float logits[EE];
    int row = blockIdx.x, tid = threadIdx.x;
    const float* p0 = x0 + (size_t)row * DM;
    const float* p1 = x1 + (size_t)row * DM;
    const float* rp = r + (size_t)row * DM;
    float v[4]; float sum = 0.0f;
    #pragma unroll
    for (int i = 0; i < 4; i++) {
        int idx = tid + i * 256;
        v[i] = (p0[idx] + p1[idx] + xb[idx]) + rp[idx];
        sum += v[i];
    }
    sum = block_reduce_sum(sum, red);
    if (tid == 0) s_mean = sum * (1.0f / DM);
    __syncthreads();
    float mean = s_mean, vs = 0.0f;
    #pragma unroll
    for (int i = 0; i < 4; i++) { float dv = v[i] - mean; vs += dv * dv; }
    vs = block_reduce_sum(vs, red);
    if (tid == 0) s_rstd = rsqrtf(vs * (1.0f / DM) + EPSL);
    __syncthreads();
    float rs = s_rstd;
    #pragma unroll
    for (int i = 0; i < 4; i++) {
        int idx = tid + i * 256;
        float o = (v[i] - mean) * rs * g[idx] + be[idx];
        out[(size_t)row * DM + idx] = o;
        out_t[(size_t)row * DM + idx] = tfr(o);
    }
    __syncthreads();

    // ---- router body ----
    int lane = tid & 31, w = tid >> 5;
    const float* op = out + (size_t)row * DM;
    float acc = 0.0f;
    for (int d = lane; d < DM; d += 32) acc += op[d] * rw[d * EE + w];
    #pragma unroll
    for (int o = 16; o; o >>= 1) acc += __shfl_xor_sync(0xFFFFFFFFu, acc, o);
    if (lane == 0) logits[w] = acc + rb[w];
    __syncthreads();
    if (tid == 0) {
        int t = row;
        float m = logits[0];
        #pragma unroll
        for (int e = 1; e < EE; e++) m = fmaxf(m, logits[e]);
        float p[EE], sm = 0.0f;
        #pragma unroll
        for (int e = 0; e < EE; e++) { p[e] = __expf(logits[e] - m); sm += p[e]; }
        float inv = 1.0f / sm;
        #pragma unroll
        for (int e = 0; e < EE; e++) { p[e] *= inv; atomicAdd(&g_imp[e], p[e]); }
        int i0 = 0;
        #pragma unroll
        for (int e = 1; e < EE; e++) if (p[e] > p[i0]) i0 = e;
        int i1 = (i0 == 0) ? 1 : 0;
        #pragma unroll
        for (int e = 0; e < EE; e++) if (e != i0 && p[e] > p[i1]) i1 = e;
        float g0 = p[i0], g1 = p[i1], gs = 1.0f / (g0 + g1);
        g0 *= gs; g1 *= gs;
        int pos = atomicAdd(&g_ecnt[i0], 1);
        g_elist[i0 * NTOK + pos] = t; g_egate[i0 * NTOK + pos] = g0;
        g_slot[i0 * NTOK + pos] = 2 * t;
        pos = atomicAdd(&g_ecnt[i1], 1);
        g_elist[i1 * NTOK + pos] = t; g_egate[i1 * NTOK + pos] = g1;
        g_slot[i1 * NTOK + pos] = 2 * t + 1;
    }
}

// ---------------- final add + layernorm over expert slots (+ lb loss) ----------------
__global__ __launch_bounds__(256) void add_ln_moe_kernel(
    const float* __restrict__ r, const float* __restrict__ g,
    const float* __restrict__ be, float* __restrict__ out,
    float* __restrict__ out_lb)
{
    __shared__ float red[32];
    __shared__ float s_mean, s_rstd;
    int row = blockIdx.x, tid = threadIdx.x;
    const float* y0 = g_ys + (size_t)(row * 2) * DM;
    const float* y1 = y0 + DM;
    const float* rp = r + (size_t)row * DM;
    float v[4]; float sum = 0.0f;
    #pragma unroll
    for (int i = 0; i < 4; i++) {
        int idx = tid + i * 256;
        v[i] = y0[idx] + y1[idx] + rp[idx];
        sum += v[i];
    }
    sum = block_reduce_sum(sum, red);
    if (tid == 0) s_mean = sum * (1.0f / DM);
    __syncthreads();
    float mean = s_mean, vs = 0.0f;
    #pragma unroll
    for (int i = 0; i < 4; i++) { float dv = v[i] - mean; vs += dv * dv; }
    vs = block_reduce_sum(vs, red);
    if (tid == 0) s_rstd = rsqrtf(vs * (1.0f / DM) + EPSL);
    __syncthreads();
    float rs = s_rstd;
    #pragma unroll
    for (int i = 0; i < 4; i++) {
        int idx = tid + i * 256;
        out[(size_t)row * DM + idx] = (v[i] - mean) * rs * g[idx] + be[idx];
    }
    if (row == 0 && tid == 0 && out_lb) {
        float lb = 0.0f;
        #pragma unroll
        for (int e = 0; e < EE; e++)
            lb += ((float)g_ecnt[e] / (float)(NTOK * 2)) * (g_imp[e] / (float)NTOK);
        out_lb[0] = (float)EE * lb;
    }
}

// ---------------- host launcher ----------------
extern "C" void kernel_launch(void* const* d_in, const int* in_sizes, int n_in,
                              void* d_out, int out_size)
{
    const float* tgt = (const float*)d_in[0];
    const float* mem = (const float*)d_in[1];
    const float *sa_wq, *sa_wk, *sa_wv, *sa_wo, *ca_wq, *ca_wk, *ca_wv, *ca_wo;
    const float *sa_bq, *sa_bk, *sa_bv, *sa_bo, *ca_bq, *ca_bk, *ca_bv, *ca_bo;
    const float *ln1g, *ln1b, *ln2g, *ln2b, *ln3g, *ln3b, *rw, *rb, *w1, *b1, *w2, *b2;

    if (in_sizes[5] == DM * DM) {
        sa_wq = (const float*)d_in[2];  sa_wk = (const float*)d_in[3];
        sa_wv = (const float*)d_in[4];  sa_wo = (const float*)d_in[5];
        ca_wq = (const float*)d_in[6];  ca_wk = (const float*)d_in[7];
        ca_wv = (const float*)d_in[8];  ca_wo = (const float*)d_in[9];
        sa_bq = (const float*)d_in[10]; sa_bk = (const float*)d_in[11];
        sa_bv = (const float*)d_in[12]; sa_bo = (const float*)d_in[13];
        ca_bq = (const float*)d_in[14]; ca_bk = (const float*)d_in[15];
        ca_bv = (const float*)d_in[16]; ca_bo = (const float*)d_in[17];
        ln1g = (const float*)d_in[18]; ln2g = (const float*)d_in[19]; ln3g = (const float*)d_in[20];
        ln1b = (const float*)d_in[21]; ln2b = (const float*)d_in[22]; ln3b = (const float*)d_in[23];
    } else {
        sa_wq = (const float*)d_in[2];  sa_wk = (const float*)d_in[3];
        sa_wv = (const float*)d_in[4];
        sa_bq = (const float*)d_in[5];  sa_bk = (const float*)d_in[6];
        sa_bv = (const float*)d_in[7];
        sa_wo = (const float*)d_in[8];  sa_bo = (const float*)d_in[9];
        ca_wq = (const float*)d_in[10]; ca_wk = (const float*)d_in[11];
        ca_wv = (const float*)d_in[12];
        ca_bq = (const float*)d_in[13]; ca_bk = (const float*)d_in[14];
        ca_bv = (const float*)d_in[15];
        ca_wo = (const float*)d_in[16]; ca_bo = (const float*)d_in[17];
        ln1g = (const float*)d_in[18]; ln1b = (const float*)d_in[19];
        ln2g = (const float*)d_in[20]; ln2b = (const float*)d_in[21];
        ln3g = (const float*)d_in[22]; ln3b = (const float*)d_in[23];
    }
    rw = (const float*)d_in[24]; rb = (const float*)d_in[25];
    w1 = (const float*)d_in[26]; b1 = (const float*)d_in[27];
    w2 = (const float*)d_in[28]; b2 = (const float*)d_in[29];

    float *q, *k, *v, *k2, *v2, *ctx, *attn, *ps, *t1, *t1t, *t2, *t2t;
    cudaGetSymbolAddress((void**)&q,    g_q);
    cudaGetSymbolAddress((void**)&k,    g_k);
    cudaGetSymbolAddress((void**)&v,    g_v);
    cudaGetSymbolAddress((void**)&k2,   g_k2);
    cudaGetSymbolAddress((void**)&v2,   g_v2);
    cudaGetSymbolAddress((void**)&ctx,  g_ctx);
    cudaGetSymbolAddress((void**)&attn, g_attn);
    cudaGetSymbolAddress((void**)&ps,   g_ps);
    cudaGetSymbolAddress((void**)&t1,   g_t1);
    cudaGetSymbolAddress((void**)&t1t,  g_t1t);
    cudaGetSymbolAddress((void**)&t2,   g_t2);
    cudaGetSymbolAddress((void**)&t2t,  g_t2t);

    float* out = (float*)d_out;

    cudaFuncSetAttribute(proj_splitk_kernel, cudaFuncAttributeMaxDynamicSharedMemorySize, GEMM_SMEM);
    cudaFuncSetAttribute(proj_qkv5_kernel,   cudaFuncAttributeMaxDynamicSharedMemorySize, GEMM_SMEM);
    cudaFuncSetAttribute(moe1_kernel,        cudaFuncAttributeMaxDynamicSharedMemorySize, GEMM_SMEM);
    cudaFuncSetAttribute(moe2_kernel,        cudaFuncAttributeMaxDynamicSharedMemorySize, GEMM_SMEM);
    cudaFuncSetAttribute(attn_tc_kernel,     cudaFuncAttributeMaxDynamicSharedMemorySize, ATC_SMEM);

    dim3 gQKV5(DM / BN, NTOK / BM, 5);     // (8, 16, 5)
    dim3 gSK  (DM / BN, NTOK / BM, 2);     // (8, 16, 2): split-K halves
    dim3 gAttn(TT / AQT, HH, BB);          // (16, 16, 4)
    dim3 gMoe1(FF / BN, NTOK / BM, EE);
    dim3 gMoe2(DM / BN, NTOK / BM, EE);

    zero_small_kernel<<<1, 32>>>();

    // ---- input-dependent projections (sa QKV + ca KV); outputs rna-rounded ----
    proj_qkv5_kernel<<<gQKV5, 256, GEMM_SMEM>>>(
        tgt, tgt, tgt, mem, mem,
        sa_wq, sa_wk, sa_wv, ca_wk, ca_wv,
        sa_bq, sa_bk, sa_bv, ca_bk, ca_bv,
        q, k, v, k2, v2, DM, DM);

    // ---- self attention ----
    attn_tc_kernel<<<gAttn, 512, ATC_SMEM>>>(q, nullptr, nullptr, k, v, ctx);
    proj_splitk_kernel<<<gSK, 256, GEMM_SMEM>>>(ctx, sa_wo, attn, ps);
    add_ln2_kernel<<<NTOK, 256>>>(attn, ps, sa_bo, tgt, ln1g, ln1b, t1, t1t);

    // ---- cross attention ----
    proj_splitk_kernel<<<gSK, 256, GEMM_SMEM>>>(t1t, ca_wq, q, ps);
    attn_tc_kernel<<<gAttn, 512, ATC_SMEM>>>(q, ps, ca_bq, k2, v2, ctx);
    proj_splitk_kernel<<<gSK, 256, GEMM_SMEM>>>(ctx, ca_wo, attn, ps);
    add_ln2_router_kernel<<<NTOK, 256>>>(attn, ps, ca_bo, t1, ln2g, ln2b, t2, t2t, rw, rb);

    // ---- MoE (sparse top-2, slot-based scatter) ----
    moe1_kernel<<<gMoe1, 256, GEMM_SMEM>>>(t2t, w1, b1);
    moe2_kernel<<<gMoe2, 256, GEMM_SMEM>>>(w2, b2);
    add_ln_moe_kernel<<<NTOK, 256>>>(t2, ln3g, ln3b, out,
        (out_size > NTOK * DM) ? (out + (size_t)NTOK * DM) : nullptr);
}

// round 17
// speedup vs baseline: 1.0075x; 1.0075x over previous
#include <cuda_runtime.h>
#include <cuda_bf16.h>
#include <math.h>
#include <stdint.h>

// ---------------- problem constants ----------------
#define BB   4
#define TT   512
#define DM   1024
#define HH   16
#define DH   64
#define FF   2048
#define EE   8
#define NTOK 2048
#define EPSL 1e-5f

// GEMM tiling (round-8 proven config)
#define BM 128
#define BN 128
#define BKT 16
#define AS_STRIDE 20
#define BS_STRIDE 136
#define NSTAGE 3
#define A_ELEMS (BM * AS_STRIDE)
#define B_ELEMS (BKT * BS_STRIDE)
#define GEMM_SMEM (NSTAGE * (A_ELEMS + B_ELEMS) * 4)   // 56832

// ---------------- static scratch ----------------
__device__ float g_q   [NTOK * DM];
__device__ float g_k   [NTOK * DM];
__device__ float g_v   [NTOK * DM];
__device__ float g_k2  [NTOK * DM];
__device__ float g_v2  [NTOK * DM];
__device__ float g_ctx [NTOK * DM];
__device__ float g_attn[NTOK * DM];
__device__ float g_ps  [NTOK * DM];     // split-K partial buffer
__device__ float g_t1  [NTOK * DM];
__device__ float g_t1t [NTOK * DM];
__device__ float g_t2  [NTOK * DM];
__device__ float g_t2t [NTOK * DM];
__device__ float g_ys  [NTOK * 2 * DM];
__device__ float g_h   [(size_t)EE * NTOK * FF];
__device__ int   g_elist[EE * NTOK];
__device__ int   g_slot [EE * NTOK];
__device__ float g_egate[EE * NTOK];
__device__ int   g_ecnt [EE];
__device__ float g_imp  [EE];

// ---------------- helpers ----------------
__device__ __forceinline__ uint32_t f2tf(float f) {
    uint32_t u;
    asm("cvt.rna.tf32.f32 %0, %1;" : "=r"(u) : "f"(f));
    return u;
}
__device__ __forceinline__ float tfr(float f) { return __uint_as_float(f2tf(f)); }

__device__ __forceinline__ void mma8(float* c, const uint32_t* a, const uint32_t* b) {
    asm volatile(
        "mma.sync.aligned.m16n8k8.row.col.f32.tf32.tf32.f32 "
        "{%0,%1,%2,%3}, {%4,%5,%6,%7}, {%8,%9}, {%0,%1,%2,%3};\n"
        : "+f"(c[0]), "+f"(c[1]), "+f"(c[2]), "+f"(c[3])
        : "r"(a[0]), "r"(a[1]), "r"(a[2]), "r"(a[3]), "r"(b[0]), "r"(b[1]));
}

__device__ __forceinline__ uint32_t smem_u32(const void* p) {
    return (uint32_t)__cvta_generic_to_shared(p);
}
__device__ __forceinline__ void cp16(uint32_t dst, const void* src, bool pred) {
    int sz = pred ? 16 : 0;
    asm volatile("cp.async.cg.shared.global [%0], [%1], 16, %2;\n"
                 :: "r"(dst), "l"(src), "r"(sz) : "memory");
}
#define CP_COMMIT  asm volatile("cp.async.commit_group;\n" ::: "memory")
#define CP_WAIT1   asm volatile("cp.async.wait_group 1;\n" ::: "memory")
#define CP_WAIT0   asm volatile("cp.async.wait_group 0;\n" ::: "memory")

__device__ __forceinline__ float block_reduce_sum(float v, float* red) {
    int lane = threadIdx.x & 31, w = threadIdx.x >> 5;
    #pragma unroll
    for (int o = 16; o; o >>= 1) v += __shfl_xor_sync(0xFFFFFFFFu, v, o);
    __syncthreads();
    if (lane == 0) red[w] = v;
    __syncthreads();
    if (w == 0) {
        v = (lane < ((int)blockDim.x >> 5)) ? red[lane] : 0.0f;
        #pragma unroll
        for (int o = 16; o; o >>= 1) v += __shfl_xor_sync(0xFFFFFFFFu, v, o);
        if (lane == 0) red[0] = v;
    }
    __syncthreads();
    return red[0];
}

// ---------------- tiny zero ----------------
__global__ void zero_small_kernel() {
    int i = threadIdx.x;
    if (i < EE) { g_ecnt[i] = 0; g_imp[i] = 0.0f; }
}

// ================= tf32 MMA GEMM core =================
// MODE 0: +bias, rna-rounded out; MODE 1: moe gather+relu, rounded out;
// MODE 2: moe slot-scatter (fp32 out); MODE 4: raw partial (fp32, no bias)
template<int MODE>
__device__ __forceinline__ void gemm_core(
    const float* __restrict__ A, const float* __restrict__ W,
    const float* __restrict__ bias, float* __restrict__ C,
    int K, int N, int row0, int col0, int koff, int Kloop,
    const int* atoks, const int* slots, const float* gates)
{
    extern __shared__ uint32_t smp[];
    uint32_t* As = smp;
    uint32_t* Bs = smp + NSTAGE * A_ELEMS;

    const int tid  = threadIdx.x;
    const int lane = tid & 31;
    const int wid  = tid >> 5;
    const int wm   = wid >> 2;
    const int wn   = wid & 3;
    const int g    = lane >> 2;
    const int tig  = lane & 3;

    const int lr0 = tid >> 2;
    const int akq = (tid & 3) * 4;
    bool p0 = true, p1 = true;
    const float *a0p, *a1p;
    if (MODE == 1) {
        int t0 = atoks[lr0], t1 = atoks[lr0 + 64];
        p0 = (t0 >= 0); p1 = (t1 >= 0);
        a0p = A + (size_t)(p0 ? t0 : 0) * K + koff + akq;
        a1p = A + (size_t)(p1 ? t1 : 0) * K + koff + akq;
    } else {
        a0p = A + (size_t)(row0 + lr0) * K + koff + akq;
        a1p = A + (size_t)(row0 + lr0 + 64) * K + koff + akq;
    }

    const int kr = tid >> 4;
    const int nq = (tid & 15) * 8;
    const float* bp = W + (size_t)(koff + kr) * N + col0 + nq;

    uint32_t sA0 = smem_u32(As) + (lr0 * AS_STRIDE + akq) * 4;
    uint32_t sA1 = sA0 + 64 * AS_STRIDE * 4;
    uint32_t sB0 = smem_u32(Bs) + (kr * BS_STRIDE + nq) * 4;

    const int nk = Kloop / BKT;

#define ISSUE(b, kti) do {                                     \
        uint32_t ao = (uint32_t)(b) * (A_ELEMS * 4);           \
        cp16(sA0 + ao, a0p + (kti) * BKT, p0);                 \
        cp16(sA1 + ao, a1p + (kti) * BKT, p1);                 \
        const float* bs_ = bp + (size_t)(kti) * BKT * N;       \
        uint32_t bo = (uint32_t)(b) * (B_ELEMS * 4);           \
        cp16(sB0 + bo, bs_, true);                             \
        cp16(sB0 + bo + 16, bs_ + 4, true);                    \
    } while (0)

    ISSUE(0, 0); CP_COMMIT;
    ISSUE(1, 1); CP_COMMIT;

    float acc[4][4][4];
    #pragma unroll
    for (int i = 0; i < 4; i++)
        #pragma unroll
        for (int j = 0; j < 4; j++)
            #pragma unroll
            for (int r = 0; r < 4; r++) acc[i][j][r] = 0.0f;

    int buf = 0;
    for (int kt = 0; kt < nk; kt++) {
        CP_WAIT1;
        __syncthreads();
        if (kt + 2 < nk) {
            int nb = buf + 2; if (nb >= NSTAGE) nb -= NSTAGE;
            ISSUE(nb, kt + 2);
        }
        CP_COMMIT;

        const uint32_t* Ab = As + buf * A_ELEMS;
        const uint32_t* Bb = Bs + buf * B_ELEMS;
        #pragma unroll
        for (int k8 = 0; k8 < 2; k8++) {
            uint32_t af[4][4], bf[4][2];
            const uint32_t* abase = Ab + (wm * 64 + g) * AS_STRIDE + k8 * 8 + tig;
            #pragma unroll
            for (int mt = 0; mt < 4; mt++) {
                const uint32_t* p = abase + mt * 16 * AS_STRIDE;
                af[mt][0] = p[0];
                af[mt][1] = p[8 * AS_STRIDE];
                af[mt][2] = p[4];
                af[mt][3] = p[8 * AS_STRIDE + 4];
            }
            const uint32_t* bbase = Bb + (k8 * 8 + tig) * BS_STRIDE + wn * 32 + g;
            #pragma unroll
            for (int nt = 0; nt < 4; nt++) {
                bf[nt][0] = bbase[nt * 8];
                bf[nt][1] = bbase[4 * BS_STRIDE + nt * 8];
            }
            #pragma unroll
            for (int mt = 0; mt < 4; mt++)
                #pragma unroll
                for (int nt = 0; nt < 4; nt++)
                    mma8(acc[mt][nt], af[mt], bf[nt]);
        }
        buf = (buf == NSTAGE - 1) ? 0 : buf + 1;
    }
#undef ISSUE

    #pragma unroll
    for (int mt = 0; mt < 4; mt++) {
        const int lr = wm * 64 + mt * 16 + g;
        #pragma unroll
        for (int nt = 0; nt < 4; nt++) {
            float* ac = acc[mt][nt];
            const int c = col0 + wn * 32 + nt * 8 + 2 * tig;
            float bc0 = 0.f, bc1 = 0.f;
            if (MODE != 4) { bc0 = bias[c]; bc1 = bias[c + 1]; }
            if (MODE == 0) {
                *(float2*)&C[(size_t)(row0 + lr) * N + c]     = make_float2(tfr(ac[0] + bc0), tfr(ac[1] + bc1));
                *(float2*)&C[(size_t)(row0 + lr + 8) * N + c] = make_float2(tfr(ac[2] + bc0), tfr(ac[3] + bc1));
            } else if (MODE == 4) {
                *(float2*)&C[(size_t)(row0 + lr) * N + c]     = make_float2(ac[0], ac[1]);
                *(float2*)&C[(size_t)(row0 + lr + 8) * N + c] = make_float2(ac[2], ac[3]);
            } else if (MODE == 1) {
                if (atoks[lr] >= 0)
                    *(float2*)&C[(size_t)(row0 + lr) * N + c] = make_float2(
                        tfr(fmaxf(ac[0] + bc0, 0.f)), tfr(fmaxf(ac[1] + bc1, 0.f)));
                if (atoks[lr + 8] >= 0)
                    *(float2*)&C[(size_t)(row0 + lr + 8) * N + c] = make_float2(
                        tfr(fmaxf(ac[2] + bc0, 0.f)), tfr(fmaxf(ac[3] + bc1, 0.f)));
            } else {
                int sid = slots[lr]; float gt = gates[lr];
                if (sid >= 0)
                    *(float2*)&C[(size_t)sid * DM + c] =
                        make_float2(gt * (ac[0] + bc0), gt * (ac[1] + bc1));
                sid = slots[lr + 8]; gt = gates[lr + 8];
                if (sid >= 0)
                    *(float2*)&C[(size_t)sid * DM + c] =
                        make_float2(gt * (ac[2] + bc0), gt * (ac[3] + bc1));
            }
        }
    }
}

// ---------------- GEMM wrappers ----------------
// split-K(2) projection: z = K-half; raw fp32 partials to C0/C1
__global__ __launch_bounds__(256, 2) void proj_splitk_kernel(
    const float* A, const float* W, float* C0, float* C1)
{
    const int z = blockIdx.z;
    float* C = (z == 0) ? C0 : C1;
    gemm_core<4>(A, W, nullptr, C, DM, DM, blockIdx.y * BM, blockIdx.x * BN,
                 z * (DM / 2), DM / 2, nullptr, nullptr, nullptr);
}

// 3-way packed projections (sa_q, sa_k, sa_v), rna-rounded outputs
__global__ __launch_bounds__(256, 2) void proj_qkv3_kernel(
    const float* A,
    const float* W0, const float* W1, const float* W2,
    const float* b0, const float* b1, const float* b2,
    float* C0, float* C1, float* C2)
{
    const int z = blockIdx.z;
    const float* W = (z == 0) ? W0 : (z == 1) ? W1 : W2;
    const float* b = (z == 0) ? b0 : (z == 1) ? b1 : b2;
    float*       C = (z == 0) ? C0 : (z == 1) ? C1 : C2;
    gemm_core<0>(A, W, b, C, DM, DM, blockIdx.y * BM, blockIdx.x * BN,
                 0, DM, nullptr, nullptr, nullptr);
}

// 2-way packed projections (ca_k, ca_v), rna-rounded outputs (side stream)
__global__ __launch_bounds__(256, 2) void proj_qkv2_kernel(
    const float* A,
    const float* W0, const float* W1,
    const float* b0, const float* b1,
    float* C0, float* C1)
{
    const int z = blockIdx.z;
    const float* W = (z == 0) ? W0 : W1;
    const float* b = (z == 0) ? b0 : b1;
    float*       C = (z == 0) ? C0 : C1;
    gemm_core<0>(A, W, b, C, DM, DM, blockIdx.y * BM, blockIdx.x * BN,
                 0, DM, nullptr, nullptr, nullptr);
}

__global__ __launch_bounds__(256, 2) void moe1_kernel(
    const float* __restrict__ X, const float* __restrict__ w1,
    const float* __restrict__ b1, int ebase)
{
    const int e = ebase + blockIdx.z;
    const int cnt = g_ecnt[e];
    const int row0 = blockIdx.y * BM;
    if (row0 >= cnt) return;
    __shared__ int toks[BM];
    if (threadIdx.x < BM) {
        int r = row0 + threadIdx.x;
        toks[threadIdx.x] = (r < cnt) ? g_elist[e * NTOK + r] : -1;
    }
    __syncthreads();
    gemm_core<1>(X, w1 + (size_t)e * DM * FF, b1 + e * FF,
                 g_h + (size_t)e * NTOK * FF,
                 DM, FF, row0, blockIdx.x * BN, 0, DM, toks, nullptr, nullptr);
}

__global__ __launch_bounds__(256, 2) void moe2_kernel(
    const float* __restrict__ w2, const float* __restrict__ b2, int ebase)
{
    const int e = ebase + blockIdx.z;
    const int cnt = g_ecnt[e];
    const int row0 = blockIdx.y * BM;
    if (row0 >= cnt) return;
    __shared__ int slts[BM];
    __shared__ float gat[BM];
    if (threadIdx.x < BM) {
        int r = row0 + threadIdx.x;
        bool ok = (r < cnt);
        slts[threadIdx.x] = ok ? g_slot[e * NTOK + r] : -1;
        gat[threadIdx.x]  = ok ? g_egate[e * NTOK + r] : 0.0f;
    }
    __syncthreads();
    gemm_core<2>(g_h + (size_t)e * NTOK * FF, w2 + (size_t)e * FF * DM,
                 b2 + e * DM, g_ys,
                 FF, DM, row0, blockIdx.x * BN, 0, FF, nullptr, slts, gat);
}

// ---------------- tensor-core attention (512 threads, cp.async double-buffered) ----------------
// Q1 != nullptr: Q operand = tfr((Q+Q1+qb) * 0.125)
#define AQT   32
#define KT2   64
#define KSTR  68
#define VSTR  72
#define KVBUF (KT2 * VSTR)
#define SSTR  516
#define QF_ELEMS (2 * 8 * 32 * 4)
#define ATC_SMEM ((QF_ELEMS + 2 * KVBUF + AQT * SSTR) * 4)   // 111104 B

__global__ __launch_bounds__(512, 2) void attn_tc_kernel(
    const float* __restrict__ Q, const float* __restrict__ Q1,
    const float* __restrict__ qb,
    const float* __restrict__ Kk, const float* __restrict__ V,
    float* __restrict__ O)
{
    extern __shared__ float am[];
    uint32_t* Qf = (uint32_t*)am;
    float* KV = am + QF_ELEMS;
    float* S  = KV + 2 * KVBUF;

    const int q0  = blockIdx.x * AQT;
    const int h   = blockIdx.y;
    const int b   = blockIdx.z;
    const int tid = threadIdx.x;
    const int lane = tid & 31;
    const int wid  = tid >> 5;
    const int wm   = wid >> 3;
    const int wn   = wid & 7;
    const int g    = lane >> 2;
    const int tig  = lane & 3;

    const int lrow = tid >> 3;
    const int lc   = (tid & 7) * 8;
    const float* ksrc = Kk + ((size_t)(b * TT) + lrow) * DM + h * DH + lc;
    const float* vsrc = V  + ((size_t)(b * TT) + lrow) * DM + h * DH + lc;
    uint32_t kdst = smem_u32(KV) + (lrow * KSTR + lc) * 4;
    uint32_t vdst = smem_u32(KV) + (lrow * VSTR + lc) * 4;

#define ISSUE_K(bf_, kt_) do {                                         \
        const float* s_ = ksrc + (size_t)(kt_) * KT2 * DM;             \
        uint32_t d_ = kdst + (uint32_t)(bf_) * (KVBUF * 4);            \
        cp16(d_, s_, true); cp16(d_ + 16, s_ + 4, true);               \
    } while (0)
#define ISSUE_V(bf_, kt_) do {                                         \
        const float* s_ = vsrc + (size_t)(kt_) * KT2 * DM;             \
        uint32_t d_ = vdst + (uint32_t)(bf_) * (KVBUF * 4);            \
        cp16(d_, s_, true); cp16(d_ + 16, s_ + 4, true);               \
    } while (0)

    ISSUE_K(0, 0); CP_COMMIT;

    for (int i = tid; i < QF_ELEMS; i += 512) {
        int r     = i & 3;
        int lane_ = (i >> 2) & 31;
        int k8    = (i >> 7) & 7;
        int wmf   = i >> 10;
        int gg = lane_ >> 2, tt = lane_ & 3;
        int row = q0 + wmf * 16 + gg + (r & 1) * 8;
        int col = k8 * 8 + tt + (r >> 1) * 4;
        size_t idx = ((size_t)(b * TT + row)) * DM + h * DH + col;
        float v;
        if (Q1) v = tfr((Q[idx] + Q1[idx] + qb[h * DH + col]) * 0.125f);
        else    v = Q[idx] * 0.125f;
        Qf[i] = __float_as_uint(v);
    }

    int buf = 0;
    for (int kt = 0; kt < TT / KT2; kt++) {
        const bool more = (kt + 1 < TT / KT2);
        if (more) { ISSUE_K(buf ^ 1, kt + 1); CP_COMMIT; }
        if (more) { CP_WAIT1; } else { CP_WAIT0; }
        __syncthreads();

        const float* Kb = KV + buf * KVBUF;
        float c[4] = {0.f, 0.f, 0.f, 0.f};
        #pragma unroll
        for (int k8 = 0; k8 < DH / 8; k8++) {
            uint32_t af[4];
            *(uint4*)af = *(const uint4*)(Qf + ((wm * 8 + k8) * 32 + lane) * 4);
            const uint32_t* bb = (const uint32_t*)(Kb + (wn * 8 + g) * KSTR + k8 * 8 + tig);
            uint32_t bf2[2] = { bb[0], bb[4] };
            mma8(c, af, bf2);
        }
        int col = kt * KT2 + wn * 8 + 2 * tig;
        float* s0 = S + (wm * 16 + g) * SSTR + col;
        float* s1 = S + (wm * 16 + g + 8) * SSTR + col;
        s0[0] = c[0]; s0[1] = c[1];
        s1[0] = c[2]; s1[1] = c[3];
        __syncthreads();
        buf ^= 1;
    }

    ISSUE_V(0, 0); CP_COMMIT;

    #pragma unroll
    for (int rr = 0; rr < 2; rr++) {
        int row = wid * 2 + rr;
        float* sr = S + row * SSTR;
        float m = -1e30f;
        for (int j = lane; j < TT; j += 32) m = fmaxf(m, sr[j]);
        #pragma unroll
        for (int o = 16; o; o >>= 1) m = fmaxf(m, __shfl_xor_sync(0xFFFFFFFFu, m, o));
        float sum = 0.0f;
        for (int j = lane; j < TT; j += 32) { float ev = __expf(sr[j] - m); sr[j] = ev; sum += ev; }
        #pragma unroll
        for (int o = 16; o; o >>= 1) sum += __shfl_xor_sync(0xFFFFFFFFu, sum, o);
        float inv = 1.0f / sum;
        for (int j = lane; j < TT; j += 32) sr[j] = tfr(sr[j] * inv);
    }

    float acc[4] = {0.f, 0.f, 0.f, 0.f};
    buf = 0;
    for (int vt = 0; vt < TT / KT2; vt++) {
        const bool more = (vt + 1 < TT / KT2);
        if (more) { ISSUE_V(buf ^ 1, vt + 1); CP_COMMIT; }
        if (more) { CP_WAIT1; } else { CP_WAIT0; }
        __syncthreads();

        const float* Vb = KV + buf * KVBUF;
        #pragma unroll
        for (int k8 = 0; k8 < KT2 / 8; k8++) {
            uint32_t af[4];
            const uint32_t* ab = (const uint32_t*)(S + (wm * 16 + g) * SSTR + vt * KT2 + k8 * 8 + tig);
            af[0] = ab[0]; af[1] = ab[8 * SSTR]; af[2] = ab[4]; af[3] = ab[8 * SSTR + 4];
            const uint32_t* bb = (const uint32_t*)(Vb + (k8 * 8 + tig) * VSTR + wn * 8 + g);
            uint32_t bf2[2] = { bb[0], bb[4 * VSTR] };
            mma8(acc, af, bf2);
        }
        __syncthreads();
        buf ^= 1;
    }
#undef ISSUE_K
#undef ISSUE_V

    {
        int col = h * DH + wn * 8 + 2 * tig;
        size_t r0 = (size_t)(b * TT + q0 + wm * 16 + g) * DM + col;
        size_t r1 = (size_t)(b * TT + q0 + wm * 16 + g + 8) * DM + col;
        O[r0]     = tfr(acc[0]); O[r0 + 1] = tfr(acc[1]);
        O[r1]     = tfr(acc[2]); O[r1 + 1] = tfr(acc[3]);
    }
}

// ---------------- add(2 partials + bias) + layernorm (dual output) ----------------
__global__ __launch_bounds__(256) void add_ln2_kernel(
    const float* __restrict__ x0, const float* __restrict__ x1,
    const float* __restrict__ xb, const float* __restrict__ r,
    const float* __restrict__ g, const float* __restrict__ be,
    float* __restrict__ out, float* __restrict__ out_t)
{
    __shared__ float red[32];
    __shared__ float s_mean, s_rstd;
    int row = blockIdx.x, tid = threadIdx.x;
    const float* p0 = x0 + (size_t)row * DM;
    const float* p1 = x1 + (size_t)row * DM;
    const float* rp = r + (size_t)row * DM;
    float v[4]; float sum = 0.0f;
    #pragma unroll
    for (int i = 0; i < 4; i++) {
        int idx = tid + i * 256;
        v[i] = (p0[idx] + p1[idx] + xb[idx]) + rp[idx];
        sum += v[i];
    }
    sum = block_reduce_sum(sum, red);
    if (tid == 0) s_mean = sum * (1.0f / DM);
    __syncthreads();
    float mean = s_mean, vs = 0.0f;
    #pragma unroll
    for (int i = 0; i < 4; i++) { float dv = v[i] - mean; vs += dv * dv; }
    vs = block_reduce_sum(vs, red);
    if (tid == 0) s_rstd = rsqrtf(vs * (1.0f / DM) + EPSL);
    __syncthreads();
    float rs = s_rstd;
    #pragma unroll
    for (int i = 0; i < 4; i++) {
        int idx = tid + i * 256;
        float o = (v[i] - mean) * rs * g[idx] + be[idx];
        out[(size_t)row * DM + idx] = o;
        if (out_t) out_t[(size_t)row * DM + idx] = tfr(o);
    }
}

// ---------------- add(2 partials + bias) + layernorm + fused router (LN2, dual out) ----------------
__global__ __launch_bounds__(256) void add_ln2_router_kernel(
    const float* __restrict__ x0, const float* __restrict__ x1,
    const float* __restrict__ xb, const float* __restrict__ r,
    const float* __restrict__ g, const float* __restrict__ be,
    float* __restrict__ out, float* __restrict__ out_t,
    const float* __restrict__ rw, const float* __restrict__ rb)
{
    __shared__ float red[32];
    __shared__ float s_mean, s_rstd;
    __shared__ float logits[EE];
    int row = blockIdx.x, tid = threadIdx.x;
    const float* p0 = x0 + (size_t)row * DM;
    const float* p1 = x1 + (size_t)row * DM;
    const float* rp = r + (size_t)row * DM;
    float v[4]; float sum = 0.0f;
    #pragma unroll
    for (int i = 0; i < 4; i++) {
        int idx = tid + i * 256;
        v[i] = (p0[idx] + p1[idx] + xb[idx]) + rp[idx];
        sum += v[i];
    }
    sum = block_reduce_sum(sum, red);
    if (tid == 0) s_mean = sum * (1.0f / DM);
    __syncthreads();
    float mean = s_mean, vs = 0.0f;
    #pragma unroll
    for (int i = 0; i < 4; i++) { float dv = v[i] - mean; vs += dv * dv; }
    vs = block_reduce_sum(vs, red);
    if (tid == 0) s_rstd = rsqrtf(vs * (1.0f / DM) + EPSL);
    __syncthreads();
    float rs = s_rstd;
    #pragma unroll
    for (int i = 0; i < 4; i++) {
        int idx = tid + i * 256;
        float o = (v[i] - mean) * rs * g[idx] + be[idx];
        out[(size_t)row * DM + idx] = o;
        out_t[(size_t)row * DM + idx] = tfr(o);
    }
    __syncthreads();

    // ---- router body ----
    int lane = tid & 31, w = tid >> 5;
    const float* op = out + (size_t)row * DM;
    float acc = 0.0f;
    for (int d = lane; d < DM; d += 32) acc += op[d] * rw[d * EE + w];
    #pragma unroll
    for (int o = 16; o; o >>= 1) acc += __shfl_xor_sync(0xFFFFFFFFu, acc, o);
    if (lane == 0) logits[w] = acc + rb[w];
    __syncthreads();
    if (tid == 0) {
        int t = row;
        float m = logits[0];
        #pragma unroll
        for (int e = 1; e < EE; e++) m = fmaxf(m, logits[e]);
        float p[EE], sm = 0.0f;
        #pragma unroll
        for (int e = 0; e < EE; e++) { p[e] = __expf(logits[e] - m); sm += p[e]; }
        float inv = 1.0f / sm;
        #pragma unroll
        for (int e = 0; e < EE; e++) { p[e] *= inv; atomicAdd(&g_imp[e], p[e]); }
        int i0 = 0;
        #pragma unroll
        for (int e = 1; e < EE; e++) if (p[e] > p[i0]) i0 = e;
        int i1 = (i0 == 0) ? 1 : 0;
        #pragma unroll
        for (int e = 0; e < EE; e++) if (e != i0 && p[e] > p[i1]) i1 = e;
        float g0 = p[i0], g1 = p[i1], gs = 1.0f / (g0 + g1);
        g0 *= gs; g1 *= gs;
        int pos = atomicAdd(&g_ecnt[i0], 1);
        g_elist[i0 * NTOK + pos] = t; g_egate[i0 * NTOK + pos] = g0;
        g_slot[i0 * NTOK + pos] = 2 * t;
        pos = atomicAdd(&g_ecnt[i1], 1);
        g_elist[i1 * NTOK + pos] = t; g_egate[i1 * NTOK + pos] = g1;
        g_slot[i1 * NTOK + pos] = 2 * t + 1;
    }
}

// ---------------- final add + layernorm over expert slots (+ lb loss) ----------------
__global__ __launch_bounds__(256) void add_ln_moe_kernel(
    const float* __restrict__ r, const float* __restrict__ g,
    const float* __restrict__ be, float* __restrict__ out,
    float* __restrict__ out_lb)
{
    __shared__ float red[32];
    __shared__ float s_mean, s_rstd;
    int row = blockIdx.x, tid = threadIdx.x;
    const float* y0 = g_ys + (size_t)(row * 2) * DM;
    const float* y1 = y0 + DM;
    const float* rp = r + (size_t)row * DM;
    float v[4]; float sum = 0.0f;
    #pragma unroll
    for (int i = 0; i < 4; i++) {
        int idx = tid + i * 256;
        v[i] = y0[idx] + y1[idx] + rp[idx];
        sum += v[i];
    }
    sum = block_reduce_sum(sum, red);
    if (tid == 0) s_mean = sum * (1.0f / DM);
    __syncthreads();
    float mean = s_mean, vs = 0.0f;
    #pragma unroll
    for (int i = 0; i < 4; i++) { float dv = v[i] - mean; vs += dv * dv; }
    vs = block_reduce_sum(vs, red);
    if (tid == 0) s_rstd = rsqrtf(vs * (1.0f / DM) + EPSL);
    __syncthreads();
    float rs = s_rstd;
    #pragma unroll
    for (int i = 0; i < 4; i++) {
        int idx = tid + i * 256;
        out[(size_t)row * DM + idx] = (v[i] - mean) * rs * g[idx] + be[idx];
    }
    if (row == 0 && tid == 0 && out_lb) {
        float lb = 0.0f;
        #pragma unroll
        for (int e = 0; e < EE; e++)
            lb += ((float)g_ecnt[e] / (float)(NTOK * 2)) * (g_imp[e] / (float)NTOK);
        out_lb[0] = (float)EE * lb;
    }
}

// ---------------- host launcher ----------------
extern "C" void kernel_launch(void* const* d_in, const int* in_sizes, int n_in,
                              void* d_out, int out_size)
{
    const float* tgt = (const float*)d_in[0];
    const float* mem = (const float*)d_in[1];
    const float *sa_wq, *sa_wk, *sa_wv, *sa_wo, *ca_wq, *ca_wk, *ca_wv, *ca_wo;
    const float *sa_bq, *sa_bk, *sa_bv, *sa_bo, *ca_bq, *ca_bk, *ca_bv, *ca_bo;
    const float *ln1g, *ln1b, *ln2g, *ln2b, *ln3g, *ln3b, *rw, *rb, *w1, *b1, *w2, *b2;

    if (in_sizes[5] == DM * DM) {
        sa_wq = (const float*)d_in[2];  sa_wk = (const float*)d_in[3];
        sa_wv = (const float*)d_in[4];  sa_wo = (const float*)d_in[5];
        ca_wq = (const float*)d_in[6];  ca_wk = (const float*)d_in[7];
        ca_wv = (const float*)d_in[8];  ca_wo = (const float*)d_in[9];
        sa_bq = (const float*)d_in[10]; sa_bk = (const float*)d_in[11];
        sa_bv = (const float*)d_in[12]; sa_bo = (const float*)d_in[13];
        ca_bq = (const float*)d_in[14]; ca_bk = (const float*)d_in[15];
        ca_bv = (const float*)d_in[16]; ca_bo = (const float*)d_in[17];
        ln1g = (const float*)d_in[18]; ln2g = (const float*)d_in[19]; ln3g = (const float*)d_in[20];
        ln1b = (const float*)d_in[21]; ln2b = (const float*)d_in[22]; ln3b = (const float*)d_in[23];
    } else {
        sa_wq = (const float*)d_in[2];  sa_wk = (const float*)d_in[3];
        sa_wv = (const float*)d_in[4];
        sa_bq = (const float*)d_in[5];  sa_bk = (const float*)d_in[6];
        sa_bv = (const float*)d_in[7];
        sa_wo = (const float*)d_in[8];  sa_bo = (const float*)d_in[9];
        ca_wq = (const float*)d_in[10]; ca_wk = (const float*)d_in[11];
        ca_wv = (const float*)d_in[12];
        ca_bq = (const float*)d_in[13]; ca_bk = (const float*)d_in[14];
        ca_bv = (const float*)d_in[15];
        ca_wo = (const float*)d_in[16]; ca_bo = (const float*)d_in[17];
        ln1g = (const float*)d_in[18]; ln1b = (const float*)d_in[19];
        ln2g = (const float*)d_in[20]; ln2b = (const float*)d_in[21];
        ln3g = (const float*)d_in[22]; ln3b = (const float*)d_in[23];
    }
    rw = (const float*)d_in[24]; rb = (const float*)d_in[25];
    w1 = (const float*)d_in[26]; b1 = (const float*)d_in[27];
    w2 = (const float*)d_in[28]; b2 = (const float*)d_in[29];

    float *q, *k, *v, *k2, *v2, *ctx, *attn, *ps, *t1, *t1t, *t2, *t2t;
    cudaGetSymbolAddress((void**)&q,    g_q);
    cudaGetSymbolAddress((void**)&k,    g_k);
    cudaGetSymbolAddress((void**)&v,    g_v);
    cudaGetSymbolAddress((void**)&k2,   g_k2);
    cudaGetSymbolAddress((void**)&v2,   g_v2);
    cudaGetSymbolAddress((void**)&ctx,  g_ctx);
    cudaGetSymbolAddress((void**)&attn, g_attn);
    cudaGetSymbolAddress((void**)&ps,   g_ps);
    cudaGetSymbolAddress((void**)&t1,   g_t1);
    cudaGetSymbolAddress((void**)&t1t,  g_t1t);
    cudaGetSymbolAddress((void**)&t2,   g_t2);
    cudaGetSymbolAddress((void**)&t2t,  g_t2t);

    float* out = (float*)d_out;

    cudaFuncSetAttribute(proj_splitk_kernel, cudaFuncAttributeMaxDynamicSharedMemorySize, GEMM_SMEM);
    cudaFuncSetAttribute(proj_qkv3_kernel,   cudaFuncAttributeMaxDynamicSharedMemorySize, GEMM_SMEM);
    cudaFuncSetAttribute(proj_qkv2_kernel,   cudaFuncAttributeMaxDynamicSharedMemorySize, GEMM_SMEM);
    cudaFuncSetAttribute(moe1_kernel,        cudaFuncAttributeMaxDynamicSharedMemorySize, GEMM_SMEM);
    cudaFuncSetAttribute(moe2_kernel,        cudaFuncAttributeMaxDynamicSharedMemorySize, GEMM_SMEM);
    cudaFuncSetAttribute(attn_tc_kernel,     cudaFuncAttributeMaxDynamicSharedMemorySize, ATC_SMEM);

    dim3 gQKV3(DM / BN, NTOK / BM, 3);     // (8, 16, 3)
    dim3 gQKV2(DM / BN, NTOK / BM, 2);     // (8, 16, 2)
    dim3 gSK  (DM / BN, NTOK / BM, 2);     // (8, 16, 2): split-K halves
    dim3 gAttn(TT / AQT, HH, BB);          // (16, 16, 4)
    dim3 gMoe1h(FF / BN, NTOK / BM, EE / 2);   // (16, 16, 4)
    dim3 gMoe2h(DM / BN, NTOK / BM, EE / 2);   // (8, 16, 4)

    // side stream + events (capture-safe fork/join)
    cudaStream_t s2;
    cudaStreamCreateWithFlags(&s2, cudaStreamNonBlocking);
    cudaEvent_t evA, evB, evC, evD;
    cudaEventCreateWithFlags(&evA, cudaEventDisableTiming);
    cudaEventCreateWithFlags(&evB, cudaEventDisableTiming);
    cudaEventCreateWithFlags(&evC, cudaEventDisableTiming);
    cudaEventCreateWithFlags(&evD, cudaEventDisableTiming);

    zero_small_kernel<<<1, 32>>>();

    // ---- fork: ca_K / ca_V projections on side stream (independent of everything) ----
    cudaEventRecord(evA, 0);
    cudaStreamWaitEvent(s2, evA, 0);
    proj_qkv2_kernel<<<gQKV2, 256, GEMM_SMEM, s2>>>(
        mem, ca_wk, ca_wv, ca_bk, ca_bv, k2, v2);
    cudaEventRecord(evB, s2);

    // ---- sa QKV projections + self attention on main stream ----
    proj_qkv3_kernel<<<gQKV3, 256, GEMM_SMEM>>>(
        tgt, sa_wq, sa_wk, sa_wv, sa_bq, sa_bk, sa_bv, q, k, v);
    attn_tc_kernel<<<gAttn, 512, ATC_SMEM>>>(q, nullptr, nullptr, k, v, ctx);
    proj_splitk_kernel<<<gSK, 256, GEMM_SMEM>>>(ctx, sa_wo, attn, ps);
    add_ln2_kernel<<<NTOK, 256>>>(attn, ps, sa_bo, tgt, ln1g, ln1b, t1, t1t);

    // ---- cross attention (join ca_KV before attn) ----
    proj_splitk_kernel<<<gSK, 256, GEMM_SMEM>>>(t1t, ca_wq, q, ps);
    cudaStreamWaitEvent(0, evB, 0);
    attn_tc_kernel<<<gAttn, 512, ATC_SMEM>>>(q, ps, ca_bq, k2, v2, ctx);
    proj_splitk_kernel<<<gSK, 256, GEMM_SMEM>>>(ctx, ca_wo, attn, ps);
    add_ln2_router_kernel<<<NTOK, 256>>>(attn, ps, ca_bo, t1, ln2g, ln2b, t2, t2t, rw, rb);

    // ---- MoE: expert halves pipelined across two streams ----
    cudaEventRecord(evC, 0);
    cudaStreamWaitEvent(s2, evC, 0);
    moe1_kernel<<<gMoe1h, 256, GEMM_SMEM, s2>>>(t2t, w1, b1, 4);
    moe2_kernel<<<gMoe2h, 256, GEMM_SMEM, s2>>>(w2, b2, 4);
    cudaEventRecord(evD, s2);
    moe1_kernel<<<gMoe1h, 256, GEMM_SMEM>>>(t2t, w1, b1, 0);
    moe2_kernel<<<gMoe2h, 256, GEMM_SMEM>>>(w2, b2, 0);
    cudaStreamWaitEvent(0, evD, 0);
    add_ln_moe_kernel<<<NTOK, 256>>>(t2, ln3g, ln3b, out,
        (out_size > NTOK * DM) ? (out + (size_t)NTOK * DM) : nullptr);

    cudaEventDestroy(evA);
    cudaEventDestroy(evB);
    cudaEventDestroy(evC);
    cudaEventDestroy(evD);
    cudaStreamDestroy(s2);
}